// round 13
// baseline (speedup 1.0000x reference)
#include <cuda_runtime.h>

// out[n,f] = kipf[n,f] - lbda[n] * input[n,f]
// 25.6M f32 = 6.4M float4. HBM-bound, ~307.6 MB minimum traffic.
// R7-R12 cluster at 39.8-41.2us kernel (~6.5-6.7 TB/s, 82-84% of spec).
// This round: single-wave persistent grid — 625 CTAs (all resident),
// 20 iterations/thread of the R8-optimal inner shape (2 f4, MLP_p1=4),
// eliminating ~10 wave transitions + tail-wave imbalance.
// 625 * 256 * 2 * 20 = 6,400,000 f4 exactly — no bounds checks.

static constexpr int NBLOCKS   = 625;
static constexpr int NTHREADS  = 256;
static constexpr int ITERS     = 20;
static constexpr unsigned PASS_STRIDE = NBLOCKS * NTHREADS * 2u;  // 320,000 f4

__global__ void __launch_bounds__(NTHREADS) damping_kernel(
    const float4* __restrict__ input4,
    const float4* __restrict__ kipf4,
    const float*  __restrict__ lbda,
    float4*       __restrict__ out4)
{
    unsigned i0 = blockIdx.x * (NTHREADS * 2u) + threadIdx.x;

#pragma unroll 1
    for (int j = 0; j < ITERS; ++j, i0 += PASS_STRIDE) {
        const unsigned i1 = i0 + NTHREADS;

        // lbda: 64 consecutive threads share one node -> warp broadcast,
        // 400 KB total -> L2 resident across the whole kernel.
        const float l0 = __ldg(&lbda[i0 >> 6]);
        const float l1 = __ldg(&lbda[i1 >> 6]);

        // 4 independent 128-bit streaming loads, front-batched (MLP_p1=4,
        // the measured knee; unroll 1 keeps queue depth at the knee).
        const float4 a0 = __ldcs(&input4[i0]);
        const float4 b0 = __ldcs(&kipf4[i0]);
        const float4 a1 = __ldcs(&input4[i1]);
        const float4 b1 = __ldcs(&kipf4[i1]);

        float4 r0, r1;
        r0.x = fmaf(-l0, a0.x, b0.x);
        r0.y = fmaf(-l0, a0.y, b0.y);
        r0.z = fmaf(-l0, a0.z, b0.z);
        r0.w = fmaf(-l0, a0.w, b0.w);
        r1.x = fmaf(-l1, a1.x, b1.x);
        r1.y = fmaf(-l1, a1.y, b1.y);
        r1.z = fmaf(-l1, a1.z, b1.z);
        r1.w = fmaf(-l1, a1.w, b1.w);

        // Streaming stores: write-once, evict-first.
        __stcs(&out4[i0], r0);
        __stcs(&out4[i1], r1);
    }
}

extern "C" void kernel_launch(void* const* d_in, const int* in_sizes, int n_in,
                              void* d_out, int out_size)
{
    const float4* input4 = (const float4*)d_in[0];
    const float4* kipf4  = (const float4*)d_in[1];
    const float*  lbda   = (const float*)d_in[2];
    float4*       out4   = (float4*)d_out;

    damping_kernel<<<NBLOCKS, NTHREADS>>>(input4, kipf4, lbda, out4);
}

// round 15
// speedup vs baseline: 1.0156x; 1.0156x over previous
#include <cuda_runtime.h>

// out[n,f] = kipf[n,f] - lbda[n] * input[n,f]
// 25.6M f32 = 6.4M float4. HBM-bound, ~307.6 MB minimum traffic (2 reads +
// 1 write, zero reuse).
//
// Final configuration after the R7-R13 sweep:
//   - 2 float4/thread, 256 threads, 12500 blocks (full occupancy, ~10 waves)
//   - MLP_p1=4 front-batched LDG.128 (the measured knee: 2 -> 40.9us,
//     4 -> 39.8us, 8 -> 41.2us via cross-CTA L1tex-queue spread)
//   - .cs streaming hints on bulk loads/stores (no L2 reuse to protect)
//   - persistent single-wave grid REGRESSED (occ 47%, DRAM 80.7%): for
//     streaming kernels wave transitions are overlapped, resident-warp
//     MLP is what fills DRAM.
// Measured ceiling: 6.5-6.7 TB/s (82-84% of 8 TB/s spec) — the realistic
// HBM3e limit for a 2:1 read:write mix. Roofline-terminal.

__global__ void __launch_bounds__(256) damping_kernel(
    const float4* __restrict__ input4,
    const float4* __restrict__ kipf4,
    const float*  __restrict__ lbda,
    float4*       __restrict__ out4)
{
    // Each block: 512 consecutive float4 (2/thread, stride 256).
    // grid = 6.4M / 512 = 12500 blocks, exact — no bounds checks.
    const unsigned i0 = blockIdx.x * 512u + threadIdx.x;
    const unsigned i1 = i0 + 256u;

    // lbda: 64 consecutive threads share one node -> warp broadcast,
    // 400 KB total -> L1/L2 resident. Default caching (it IS reused).
    const float l0 = __ldg(&lbda[i0 >> 6]);
    const float l1 = __ldg(&lbda[i1 >> 6]);

    // 4 independent 128-bit streaming loads, front-batched (MLP_p1=4).
    const float4 a0 = __ldcs(&input4[i0]);
    const float4 b0 = __ldcs(&kipf4[i0]);
    const float4 a1 = __ldcs(&input4[i1]);
    const float4 b1 = __ldcs(&kipf4[i1]);

    float4 r0, r1;
    r0.x = fmaf(-l0, a0.x, b0.x);
    r0.y = fmaf(-l0, a0.y, b0.y);
    r0.z = fmaf(-l0, a0.z, b0.z);
    r0.w = fmaf(-l0, a0.w, b0.w);
    r1.x = fmaf(-l1, a1.x, b1.x);
    r1.y = fmaf(-l1, a1.y, b1.y);
    r1.z = fmaf(-l1, a1.z, b1.z);
    r1.w = fmaf(-l1, a1.w, b1.w);

    // Streaming stores: write-once, evict-first (don't pollute L2 ways).
    __stcs(&out4[i0], r0);
    __stcs(&out4[i1], r1);
}

extern "C" void kernel_launch(void* const* d_in, const int* in_sizes, int n_in,
                              void* d_out, int out_size)
{
    const float4* input4 = (const float4*)d_in[0];
    const float4* kipf4  = (const float4*)d_in[1];
    const float*  lbda   = (const float*)d_in[2];
    float4*       out4   = (float4*)d_out;

    const int total_f4 = in_sizes[0] / 4;                      // 6,400,000
    const int blocks = (total_f4 + 511) / 512;                 // 12,500

    damping_kernel<<<blocks, 256>>>(input4, kipf4, lbda, out4);
}